// round 14
// baseline (speedup 1.0000x reference)
#include <cuda_runtime.h>
#include <cuda_fp16.h>
#include <math_constants.h>
#include <cstdint>

#define B_    256
#define N_    196
#define DIM_  576
#define NH_   18
#define KD_   32
#define DV_   128
#define HSZ_  192
#define HOUT_ 3456
#define DH_   2304
#define MT_   (B_*N_)      // 50176 rows
#define NP_   208          // padded attention length (13*16)

// Scratch (allocation-free rule: static __device__ arrays)
__device__ __half g_xn [(size_t)MT_ * DIM_];        // normalized x (fp16)
__device__ __half g_qkv[(size_t)MT_ * HOUT_];       // qkv projection (fp16)
__device__ __half g_ao [(size_t)MT_ * DH_];         // attention output (fp16)
__device__ __half g_wqkvt [(size_t)HOUT_ * DIM_];   // w_qkv^T  [3456,576]
__device__ __half g_wprojt[(size_t)DIM_ * DH_];     // w_proj^T [576,2304]
__device__ float  g_biasf [(size_t)NH_ * N_ * NP_]; // bias*log2e (fp32), pad=-1e30

// ---------------------------------------------------------------------------
// helpers
// ---------------------------------------------------------------------------
__device__ __forceinline__ uint32_t smem_to_u32(const void* p) {
    uint32_t a;
    asm("{ .reg .u64 t; cvta.to.shared.u64 t, %1; cvt.u32.u64 %0, t; }"
        : "=r"(a) : "l"(p));
    return a;
}
__device__ __forceinline__ void cp16(uint32_t dst, const void* src) {
    asm volatile("cp.async.cg.shared.global [%0], [%1], 16;" :: "r"(dst), "l"(src));
}
__device__ __forceinline__ void cp_commit() {
    asm volatile("cp.async.commit_group;" ::: "memory");
}
template<int n> __device__ __forceinline__ void cp_wait() {
    asm volatile("cp.async.wait_group %0;" :: "n"(n) : "memory");
}
__device__ __forceinline__ void mma_f16(float* d, const uint32_t* a,
                                        uint32_t b0, uint32_t b1) {
    asm volatile(
        "mma.sync.aligned.m16n8k16.row.col.f32.f16.f16.f32 "
        "{%0,%1,%2,%3}, {%4,%5,%6,%7}, {%8,%9}, {%0,%1,%2,%3};\n"
        : "+f"(d[0]), "+f"(d[1]), "+f"(d[2]), "+f"(d[3])
        : "r"(a[0]), "r"(a[1]), "r"(a[2]), "r"(a[3]), "r"(b0), "r"(b1));
}
__device__ __forceinline__ void ldsm_x4(uint32_t* r, uint32_t addr) {
    asm volatile("ldmatrix.sync.aligned.m8n8.x4.shared.b16 {%0,%1,%2,%3}, [%4];"
                 : "=r"(r[0]), "=r"(r[1]), "=r"(r[2]), "=r"(r[3]) : "r"(addr));
}
__device__ __forceinline__ void ldsm_x4_t(uint32_t* r, uint32_t addr) {
    asm volatile("ldmatrix.sync.aligned.m8n8.x4.trans.shared.b16 {%0,%1,%2,%3}, [%4];"
                 : "=r"(r[0]), "=r"(r[1]), "=r"(r[2]), "=r"(r[3]) : "r"(addr));
}
__device__ __forceinline__ float ex2f(float x) {
    float y;
    asm("ex2.approx.ftz.f32 %0, %1;" : "=f"(y) : "f"(x));
    return y;
}

// ---------------------------------------------------------------------------
// Weight transpose to fp16: src[R][C] (fp32) -> dst[C][R] (fp16)
// ---------------------------------------------------------------------------
__global__ void __launch_bounds__(256) transpose_h(
    const float* __restrict__ src, __half* __restrict__ dst, int R, int C)
{
    __shared__ float t[32][33];
    const int bx = blockIdx.x * 32;
    const int by = blockIdx.y * 32;
    const int tx = threadIdx.x, ty = threadIdx.y;
    #pragma unroll
    for (int i = 0; i < 32; i += 8)
        t[ty + i][tx] = src[(size_t)(by + ty + i) * C + bx + tx];
    __syncthreads();
    #pragma unroll
    for (int i = 0; i < 32; i += 8)
        dst[(size_t)(bx + ty + i) * R + by + tx] = __float2half_rn(t[tx][ty + i]);
}

// ---------------------------------------------------------------------------
// Bias expansion: g_biasf[h][i][j] = ab[h][idxs[i][j]] * log2e; pad = -1e30
// ---------------------------------------------------------------------------
__global__ void __launch_bounds__(256) bias_expand(
    const float* __restrict__ ab, const int* __restrict__ idxs, int offsz)
{
    const int i = blockIdx.x;
    const int h = blockIdx.y;
    const float* abh = ab + (size_t)h * offsz;
    float* dst = g_biasf + ((size_t)h * N_ + i) * NP_;
    for (int j = threadIdx.x; j < NP_; j += 256)
        dst[j] = (j < N_) ? abh[idxs[i * N_ + j]] * 1.4426950408889634f
                          : -1e30f;
}

// ---------------------------------------------------------------------------
// LayerNorm: one block per row (576 elems), output fp16
// ---------------------------------------------------------------------------
__global__ void __launch_bounds__(256) ln_kernel(const float* __restrict__ x,
                                                 const float* __restrict__ w,
                                                 const float* __restrict__ b)
{
    const int row = blockIdx.x;
    const float* xr = x    + (size_t)row * DIM_;
    __half*      xo = g_xn + (size_t)row * DIM_;
    const int tid = threadIdx.x;

    float v0 = xr[tid];
    float v1 = xr[tid + 256];
    float v2 = (tid < 64) ? xr[tid + 512] : 0.f;
    float s  = v0 + v1 + v2;
    float ss = v0*v0 + v1*v1 + v2*v2;

    #pragma unroll
    for (int o = 16; o; o >>= 1) {
        s  += __shfl_xor_sync(0xffffffffu, s,  o);
        ss += __shfl_xor_sync(0xffffffffu, ss, o);
    }
    __shared__ float sh[16];
    __shared__ float s_mu, s_rstd;
    const int warp = tid >> 5, lane = tid & 31;
    if (lane == 0) { sh[warp] = s; sh[warp + 8] = ss; }
    __syncthreads();
    if (tid == 0) {
        float ts = 0.f, tss = 0.f;
        #pragma unroll
        for (int i = 0; i < 8; i++) { ts += sh[i]; tss += sh[i + 8]; }
        float mu  = ts * (1.0f / DIM_);
        float var = tss * (1.0f / DIM_) - mu * mu;
        s_mu = mu;
        s_rstd = rsqrtf(var + 1e-5f);
    }
    __syncthreads();
    const float mu = s_mu, rstd = s_rstd;
    xo[tid]       = __float2half_rn((v0 - mu) * rstd * w[tid]       + b[tid]);
    xo[tid + 256] = __float2half_rn((v1 - mu) * rstd * w[tid + 256] + b[tid + 256]);
    if (tid < 64)
        xo[tid + 512] = __float2half_rn((v2 - mu) * rstd * w[tid + 512] + b[tid + 512]);
}

// ---------------------------------------------------------------------------
// fp16 mma.sync GEMM (templated output): C = A @ Bt^T + bias
// BM=128, BN=192, BK=32, 4-stage cp.async, 8 warps, warp tile 64x48. 2 CTA/SM.
// A: 4x ldmatrix.x4 (round-12 config); B: scalar LDS per-ni.
// Single barrier per mainloop iteration (trailing barrier proven redundant:
// the top barrier of iter c already orders all reads of stage (c+3)&3 from
// iter c-1 before the stage-(c+3)&3 loads of iter c).
// ---------------------------------------------------------------------------
#define STG_      4
#define AROW_H    40
#define AROW_W    20
#define A_TILE_H  (128 * AROW_H)
#define B_TILE_H  (192 * AROW_H)
#define ST_H      (A_TILE_H + B_TILE_H)
#define GEMM_SMEM (STG_ * ST_H * 2)         // 102400 bytes

__device__ __forceinline__ void store2(float* p, float x, float y) {
    *(float2*)p = make_float2(x, y);
}
__device__ __forceinline__ void store2(__half* p, float x, float y) {
    *(__half2*)p = __floats2half2_rn(x, y);
}

template <typename OT>
__global__ void __launch_bounds__(256, 2) gemm_mma(
    const __half* __restrict__ A, const __half* __restrict__ Bt,
    const float* __restrict__ bias, OT* __restrict__ C,
    int N, int K)
{
    extern __shared__ __half smh[];
    const uint32_t smb = smem_to_u32(smh);

    const int tid  = threadIdx.x;
    const int wid  = tid >> 5, lane = tid & 31;
    const int bm   = blockIdx.y * 128;
    const int bn   = blockIdx.x * 192;
    const int wm   = (wid & 1) * 64;
    const int wn   = (wid >> 1) * 48;
    const int NC   = K >> 5;

    float acc[4][6][4];
    #pragma unroll
    for (int mi = 0; mi < 4; mi++)
        #pragma unroll
        for (int ni = 0; ni < 6; ni++)
            #pragma unroll
            for (int r = 0; r < 4; r++) acc[mi][ni][r] = 0.f;

    const __half* Abase  = A  + (size_t)bm * K;
    const __half* Btbase = Bt + (size_t)bn * K;

    auto load_chunk = [&](int c, int st) {
        const int k0 = c * 32;
        const uint32_t abase = smb + (st * ST_H) * 2;
        const uint32_t bbase = abase + A_TILE_H * 2;
        #pragma unroll
        for (int i = 0; i < 5; i++) {
            int u = tid + i * 256;
            if (u < 512) {
                int r = u >> 2, c4 = u & 3;
                cp16(abase + (r * AROW_H + c4 * 8) * 2,
                     Abase + (size_t)r * K + k0 + c4 * 8);
            } else {
                int w = u - 512, r = w >> 2, c4 = w & 3;
                cp16(bbase + (r * AROW_H + c4 * 8) * 2,
                     Btbase + (size_t)r * K + k0 + c4 * 8);
            }
        }
    };

    load_chunk(0, 0); cp_commit();
    if (NC > 1) load_chunk(1, 1);
    cp_commit();
    if (NC > 2) load_chunk(2, 2);
    cp_commit();

    const int lr = lane >> 2;
    const int lc = lane & 3;
    const int l16 = lane & 15;         // ldmatrix row within 16-row tile
    const int lhi = (lane >> 4) << 3;  // +8 halves for k8..15 matrices

    for (int c = 0; c < NC; c++) {
        cp_wait<2>();
        __syncthreads();               // sole barrier per iteration
        if (c + 3 < NC) load_chunk(c + 3, (c + 3) & 3);
        cp_commit();

        const int st = c & 3;
        const uint32_t stA = smb + (st * ST_H) * 2;
        const uint32_t* Bsu = (const uint32_t*)(smh + st * ST_H + A_TILE_H);

        #pragma unroll
        for (int ks = 0; ks < 2; ks++) {
            const int kw = ks * 8 + lc;
            // A fragments: one ldmatrix.x4 per 16x16 m-tile
            uint32_t af[4][4];
            #pragma unroll
            for (int mi = 0; mi < 4; mi++) {
                uint32_t addr = stA +
                    (uint32_t)(((wm + mi * 16 + l16) * AROW_H) + ks * 16 + lhi) * 2;
                ldsm_x4(af[mi], addr);
            }
            // B fragments: scalar LDS, consumed per-ni (2 words live)
            #pragma unroll
            for (int ni = 0; ni < 6; ni++) {
                const int n0 = wn + ni * 8 + lr;
                const uint32_t b0 = Bsu[n0 * AROW_W + kw];
                const uint32_t b1 = Bsu[n0 * AROW_W + kw + 4];
                #pragma unroll
                for (int mi = 0; mi < 4; mi++)
                    mma_f16(acc[mi][ni], af[mi], b0, b1);
            }
        }
        // no trailing __syncthreads(): top barrier of next iter suffices
    }

    #pragma unroll
    for (int mi = 0; mi < 4; mi++) {
        const int r0 = bm + wm + mi * 16 + lr;
        #pragma unroll
        for (int ni = 0; ni < 6; ni++) {
            const int cc = bn + wn + ni * 8 + lc * 2;
            const float b0 = bias[cc], b1 = bias[cc + 1];
            store2(C + (size_t)r0 * N + cc, acc[mi][ni][0] + b0, acc[mi][ni][1] + b1);
            store2(C + (size_t)(r0 + 8) * N + cc, acc[mi][ni][2] + b0, acc[mi][ni][3] + b1);
        }
    }
}

// ---------------------------------------------------------------------------
// Tensor-core attention, fp32 softmax. One block per (b, h), 13 warps,
// each warp one 16-row m-tile of the padded 208-row problem.
// ---------------------------------------------------------------------------
#define ATN_THREADS 416
#define QSTR  40           // halves per Q/K row (20 words)
#define VROW  136          // halves per V row (128 + pad for bank skew)
#define SM_Q  0
#define SM_K  (NP_ * QSTR)             // 8320 halves
#define SM_V  (2 * NP_ * QSTR)         // 16640 halves
#define ATT_SMEM ((SM_V + NP_ * VROW) * 2)   // 89856 bytes

__global__ void __launch_bounds__(ATN_THREADS, 1) attn_mma(
    const __half* __restrict__ qkv)
{
    extern __shared__ __align__(16) __half smh[];
    const uint32_t smb = smem_to_u32(smh);
    const int h = blockIdx.x % NH_;
    const int b = blockIdx.x / NH_;
    const int tid = threadIdx.x;
    const size_t base = (size_t)(b * N_) * HOUT_ + (size_t)h * HSZ_;

    // ---- Q,K: 208 rows x 32 halves each ----
    for (int u = tid; u < NP_ * 8; u += ATN_THREADS) {
        int j = u >> 3, c = u & 7;
        int ko = (c >= 4);
        int t  = c & 3;
        int off = (ko ? SM_K : SM_Q) + j * QSTR + t * 8;
        if (j < N_) cp16(smb + off * 2,
                         qkv + base + (size_t)j * HOUT_ + ko * 32 + t * 8);
        else *(float4*)(smh + off) = make_float4(0.f, 0.f, 0.f, 0.f);
    }
    // ---- V: 208 rows x 128 halves ----
    for (int u = tid; u < NP_ * 16; u += ATN_THREADS) {
        int j = u >> 4, c = u & 15;
        int off = SM_V + j * VROW + c * 8;
        if (j < N_) cp16(smb + off * 2,
                         qkv + base + (size_t)j * HOUT_ + 64 + c * 8);
        else *(float4*)(smh + off) = make_float4(0.f, 0.f, 0.f, 0.f);
    }
    cp_commit();
    cp_wait<0>();
    __syncthreads();

    const int w    = tid >> 5;          // 0..12
    const int lane = tid & 31;
    const int lr = lane >> 2, lc = lane & 3;
    const int m0 = w * 16;
    const int r0 = m0 + lr, r1 = r0 + 8;
    const bool vr0 = (r0 < N_), vr1 = (r1 < N_);

    const uint32_t* Qw = (const uint32_t*)(smh + SM_Q);
    const uint32_t* Kw = (const uint32_t*)(smh + SM_K);

    // Q fragments (k-tiles 0,1)
    uint32_t aq[2][4];
    #pragma unroll
    for (int kt = 0; kt < 2; kt++) {
        aq[kt][0] = Qw[r0 * 20 + kt * 8 + lc];
        aq[kt][1] = Qw[r1 * 20 + kt * 8 + lc];
        aq[kt][2] = Qw[r0 * 20 + kt * 8 + lc + 4];
        aq[kt][3] = Qw[r1 * 20 + kt * 8 + lc + 4];
    }

    const float* bias0 = g_biasf + ((size_t)h * N_ + (vr0 ? r0 : 0)) * NP_ + 2 * lc;
    const float* bias1 = g_biasf + ((size_t)h * N_ + (vr1 ? r1 : 0)) * NP_ + 2 * lc;
    const float ksc = 0.25505653946178563f;   // 32^-0.5 * log2(e)

    // ---- pass 1: row maxes (fp32) ----
    float mA = -1e30f, mB = -1e30f;
    #pragma unroll
    for (int nt = 0; nt < 26; nt++) {
        float s[4] = {0.f, 0.f, 0.f, 0.f};
        #pragma unroll
        for (int kt = 0; kt < 2; kt++) {
            uint32_t b0 = Kw[(nt * 8 + lr) * 20 + kt * 8 + lc];
            uint32_t b1 = Kw[(nt * 8 + lr) * 20 + kt * 8 + lc + 4];
            mma_f16(s, aq[kt], b0, b1);
        }
        const float2 bb0 = *(const float2*)(bias0 + nt * 8);
        const float2 bb1 = *(const float2*)(bias1 + nt * 8);
        mA = fmaxf(mA, fmaxf(fmaf(s[0], ksc, bb0.x), fmaf(s[1], ksc, bb0.y)));
        mB = fmaxf(mB, fmaxf(fmaf(s[2], ksc, bb1.x), fmaf(s[3], ksc, bb1.y)));
    }
    #pragma unroll
    for (int o = 1; o <= 2; o <<= 1) {
        mA = fmaxf(mA, __shfl_xor_sync(0xffffffffu, mA, o));
        mB = fmaxf(mB, __shfl_xor_sync(0xffffffffu, mB, o));
    }

    // ---- pass 2: P = ex2(y - max) fp32, pack to half; fp32 row sums ----
    uint32_t p01[26], p23[26];
    float sA = 0.f, sB = 0.f;
    #pragma unroll
    for (int nt = 0; nt < 26; nt++) {
        float s[4] = {0.f, 0.f, 0.f, 0.f};
        #pragma unroll
        for (int kt = 0; kt < 2; kt++) {
            uint32_t b0 = Kw[(nt * 8 + lr) * 20 + kt * 8 + lc];
            uint32_t b1 = Kw[(nt * 8 + lr) * 20 + kt * 8 + lc + 4];
            mma_f16(s, aq[kt], b0, b1);
        }
        const float2 bb0 = *(const float2*)(bias0 + nt * 8);
        const float2 bb1 = *(const float2*)(bias1 + nt * 8);
        float e0 = ex2f(fmaf(s[0], ksc, bb0.x) - mA);
        float e1 = ex2f(fmaf(s[1], ksc, bb0.y) - mA);
        float e2 = ex2f(fmaf(s[2], ksc, bb1.x) - mB);
        float e3 = ex2f(fmaf(s[3], ksc, bb1.y) - mB);
        __half2 h01 = __floats2half2_rn(e0, e1);
        __half2 h23 = __floats2half2_rn(e2, e3);
        p01[nt] = *(uint32_t*)&h01;
        p23[nt] = *(uint32_t*)&h23;
        sA += e0 + e1;
        sB += e2 + e3;
    }
    #pragma unroll
    for (int o = 1; o <= 2; o <<= 1) {
        sA += __shfl_xor_sync(0xffffffffu, sA, o);
        sB += __shfl_xor_sync(0xffffffffu, sB, o);
    }
    const float inva = __fdividef(1.f, sA);
    const float invb = __fdividef(1.f, sB);

    // ---- O = P V (8 groups of 16 cols), normalize at store ----
    const uint32_t vbytes = smb + SM_V * 2;
    const uint32_t lrow = (uint32_t)(lane & 15);
    const uint32_t lcol = (uint32_t)((lane >> 4) << 3);
    const size_t orow0 = ((size_t)(b * N_) + r0) * DH_ + h * DV_;
    const size_t orow1 = ((size_t)(b * N_) + r1) * DH_ + h * DV_;
    #pragma unroll
    for (int dg = 0; dg < 8; dg++) {
        float o2[8] = {0.f,0.f,0.f,0.f,0.f,0.f,0.f,0.f};
        uint32_t a32 = vbytes + (lrow * VROW + (uint32_t)dg * 16 + lcol) * 2;
        #pragma unroll
        for (int kt = 0; kt < 13; kt++) {
            uint32_t br[4];
            ldsm_x4_t(br, a32 + (uint32_t)kt * (16 * VROW * 2));
            uint32_t af[4] = { p01[2*kt], p23[2*kt], p01[2*kt+1], p23[2*kt+1] };
            mma_f16(o2,     af, br[0], br[1]);
            mma_f16(o2 + 4, af, br[2], br[3]);
        }
        const int c0 = dg * 16 + lc * 2;
        const int c1 = c0 + 8;
        if (vr0) {
            *(__half2*)(g_ao + orow0 + c0) = __floats2half2_rn(o2[0]*inva, o2[1]*inva);
            *(__half2*)(g_ao + orow0 + c1) = __floats2half2_rn(o2[4]*inva, o2[5]*inva);
        }
        if (vr1) {
            *(__half2*)(g_ao + orow1 + c0) = __floats2half2_rn(o2[2]*invb, o2[3]*invb);
            *(__half2*)(g_ao + orow1 + c1) = __floats2half2_rn(o2[6]*invb, o2[7]*invb);
        }
    }
}

// ---------------------------------------------------------------------------
extern "C" void kernel_launch(void* const* d_in, const int* in_sizes, int n_in,
                              void* d_out, int out_size)
{
    const float* x      = (const float*)d_in[0];
    const float* ln_w   = (const float*)d_in[1];
    const float* ln_b   = (const float*)d_in[2];
    const float* w_qkv  = (const float*)d_in[3];
    const float* b_qkv  = (const float*)d_in[4];
    const float* w_proj = (const float*)d_in[5];
    const float* b_proj = (const float*)d_in[6];
    const float* ab     = (const float*)d_in[7];
    const int*   idxs   = (const int*)d_in[8];
    float* out = (float*)d_out;
    const int offsz = in_sizes[7] / NH_;

    __half *xn_p, *qkv_p, *ao_p, *wqkvt_p, *wprojt_p;
    cudaGetSymbolAddress((void**)&xn_p,     g_xn);
    cudaGetSymbolAddress((void**)&qkv_p,    g_qkv);
    cudaGetSymbolAddress((void**)&ao_p,     g_ao);
    cudaGetSymbolAddress((void**)&wqkvt_p,  g_wqkvt);
    cudaGetSymbolAddress((void**)&wprojt_p, g_wprojt);

    // 0) Weight transposes (fp32 -> fp16) and bias expansion
    transpose_h<<<dim3(HOUT_ / 32, DIM_ / 32), dim3(32, 8)>>>(
        w_qkv, wqkvt_p, DIM_, HOUT_);
    transpose_h<<<dim3(DIM_ / 32, DH_ / 32), dim3(32, 8)>>>(
        w_proj, wprojt_p, DH_, DIM_);
    bias_expand<<<dim3(N_, NH_), 256>>>(ab, idxs, offsz);

    // 1) LayerNorm (fp16 out)
    ln_kernel<<<MT_, 256>>>(x, ln_w, ln_b);

    // 2) QKV GEMM: [50176,576] @ [576,3456] -> fp16
    cudaFuncSetAttribute(gemm_mma<__half>,
                         cudaFuncAttributeMaxDynamicSharedMemorySize, GEMM_SMEM);
    gemm_mma<__half><<<dim3(HOUT_ / 192, MT_ / 128), 256, GEMM_SMEM>>>(
        xn_p, wqkvt_p, b_qkv, qkv_p, HOUT_, DIM_);

    // 3) Tensor-core attention per (b, h)
    cudaFuncSetAttribute(attn_mma,
                         cudaFuncAttributeMaxDynamicSharedMemorySize, ATT_SMEM);
    attn_mma<<<B_ * NH_, ATN_THREADS, ATT_SMEM>>>(qkv_p);

    // 4) Projection GEMM: [50176,2304] @ [2304,576] -> fp32 output
    cudaFuncSetAttribute(gemm_mma<float>,
                         cudaFuncAttributeMaxDynamicSharedMemorySize, GEMM_SMEM);
    gemm_mma<float><<<dim3(DIM_ / 192, MT_ / 128), 256, GEMM_SMEM>>>(
        ao_p, wprojt_p, b_proj, out, DIM_, DH_);

    (void)n_in; (void)out_size;
}

// round 15
// speedup vs baseline: 1.5202x; 1.5202x over previous
#include <cuda_runtime.h>
#include <cuda_fp16.h>
#include <math_constants.h>
#include <cstdint>

#define B_    256
#define N_    196
#define DIM_  576
#define NH_   18
#define KD_   32
#define DV_   128
#define HSZ_  192
#define HOUT_ 3456
#define DH_   2304
#define MT_   (B_*N_)      // 50176 rows
#define NP_   208          // padded attention length (13*16)

// Scratch (allocation-free rule: static __device__ arrays)
__device__ __half g_xn [(size_t)MT_ * DIM_];        // normalized x (fp16)
__device__ __half g_qkv[(size_t)MT_ * HOUT_];       // qkv projection (fp16)
__device__ __half g_ao [(size_t)MT_ * DH_];         // attention output (fp16)
__device__ __half g_wqkvt [(size_t)HOUT_ * DIM_];   // w_qkv^T  [3456,576]
__device__ __half g_wprojt[(size_t)DIM_ * DH_];     // w_proj^T [576,2304]
__device__ float  g_biasf [(size_t)NH_ * N_ * NP_]; // bias*log2e (fp32), pad=-1e30

// ---------------------------------------------------------------------------
// helpers
// ---------------------------------------------------------------------------
__device__ __forceinline__ uint32_t smem_to_u32(const void* p) {
    uint32_t a;
    asm("{ .reg .u64 t; cvta.to.shared.u64 t, %1; cvt.u32.u64 %0, t; }"
        : "=r"(a) : "l"(p));
    return a;
}
__device__ __forceinline__ void cp16(uint32_t dst, const void* src) {
    asm volatile("cp.async.cg.shared.global [%0], [%1], 16;" :: "r"(dst), "l"(src));
}
__device__ __forceinline__ void cp_commit() {
    asm volatile("cp.async.commit_group;" ::: "memory");
}
template<int n> __device__ __forceinline__ void cp_wait() {
    asm volatile("cp.async.wait_group %0;" :: "n"(n) : "memory");
}
__device__ __forceinline__ void mma_f16(float* d, const uint32_t* a,
                                        uint32_t b0, uint32_t b1) {
    asm volatile(
        "mma.sync.aligned.m16n8k16.row.col.f32.f16.f16.f32 "
        "{%0,%1,%2,%3}, {%4,%5,%6,%7}, {%8,%9}, {%0,%1,%2,%3};\n"
        : "+f"(d[0]), "+f"(d[1]), "+f"(d[2]), "+f"(d[3])
        : "r"(a[0]), "r"(a[1]), "r"(a[2]), "r"(a[3]), "r"(b0), "r"(b1));
}
__device__ __forceinline__ void ldsm_x4(uint32_t* r, uint32_t addr) {
    asm volatile("ldmatrix.sync.aligned.m8n8.x4.shared.b16 {%0,%1,%2,%3}, [%4];"
                 : "=r"(r[0]), "=r"(r[1]), "=r"(r[2]), "=r"(r[3]) : "r"(addr));
}
__device__ __forceinline__ void ldsm_x4_t(uint32_t* r, uint32_t addr) {
    asm volatile("ldmatrix.sync.aligned.m8n8.x4.trans.shared.b16 {%0,%1,%2,%3}, [%4];"
                 : "=r"(r[0]), "=r"(r[1]), "=r"(r[2]), "=r"(r[3]) : "r"(addr));
}
__device__ __forceinline__ float ex2f(float x) {
    float y;
    asm("ex2.approx.ftz.f32 %0, %1;" : "=f"(y) : "f"(x));
    return y;
}

// ---------------------------------------------------------------------------
// Weight transpose to fp16: src[R][C] (fp32) -> dst[C][R] (fp16)
// ---------------------------------------------------------------------------
__global__ void __launch_bounds__(256) transpose_h(
    const float* __restrict__ src, __half* __restrict__ dst, int R, int C)
{
    __shared__ float t[32][33];
    const int bx = blockIdx.x * 32;
    const int by = blockIdx.y * 32;
    const int tx = threadIdx.x, ty = threadIdx.y;
    #pragma unroll
    for (int i = 0; i < 32; i += 8)
        t[ty + i][tx] = src[(size_t)(by + ty + i) * C + bx + tx];
    __syncthreads();
    #pragma unroll
    for (int i = 0; i < 32; i += 8)
        dst[(size_t)(bx + ty + i) * R + by + tx] = __float2half_rn(t[tx][ty + i]);
}

// ---------------------------------------------------------------------------
// Bias expansion: g_biasf[h][i][j] = ab[h][idxs[i][j]] * log2e; pad = -1e30
// ---------------------------------------------------------------------------
__global__ void __launch_bounds__(256) bias_expand(
    const float* __restrict__ ab, const int* __restrict__ idxs, int offsz)
{
    const int i = blockIdx.x;
    const int h = blockIdx.y;
    const float* abh = ab + (size_t)h * offsz;
    float* dst = g_biasf + ((size_t)h * N_ + i) * NP_;
    for (int j = threadIdx.x; j < NP_; j += 256)
        dst[j] = (j < N_) ? abh[idxs[i * N_ + j]] * 1.4426950408889634f
                          : -1e30f;
}

// ---------------------------------------------------------------------------
// LayerNorm: one block per row (576 elems), float2 loads, output fp16
// ---------------------------------------------------------------------------
__global__ void __launch_bounds__(256) ln_kernel(const float* __restrict__ x,
                                                 const float* __restrict__ w,
                                                 const float* __restrict__ b)
{
    const int row = blockIdx.x;
    const float* xr = x    + (size_t)row * DIM_;
    __half*      xo = g_xn + (size_t)row * DIM_;
    const int tid = threadIdx.x;

    const float2 v01 = *(const float2*)(xr + tid * 2);          // 0..511
    float2 v23 = make_float2(0.f, 0.f);
    if (tid < 32) v23 = *(const float2*)(xr + 512 + tid * 2);   // 512..575

    float s  = v01.x + v01.y + v23.x + v23.y;
    float ss = v01.x*v01.x + v01.y*v01.y + v23.x*v23.x + v23.y*v23.y;

    #pragma unroll
    for (int o = 16; o; o >>= 1) {
        s  += __shfl_xor_sync(0xffffffffu, s,  o);
        ss += __shfl_xor_sync(0xffffffffu, ss, o);
    }
    __shared__ float sh[16];
    __shared__ float s_mu, s_rstd;
    const int warp = tid >> 5, lane = tid & 31;
    if (lane == 0) { sh[warp] = s; sh[warp + 8] = ss; }
    __syncthreads();
    if (tid == 0) {
        float ts = 0.f, tss = 0.f;
        #pragma unroll
        for (int i = 0; i < 8; i++) { ts += sh[i]; tss += sh[i + 8]; }
        float mu  = ts * (1.0f / DIM_);
        float var = tss * (1.0f / DIM_) - mu * mu;
        s_mu = mu;
        s_rstd = rsqrtf(var + 1e-5f);
    }
    __syncthreads();
    const float mu = s_mu, rstd = s_rstd;

    const float2 w01 = *(const float2*)(w + tid * 2);
    const float2 b01 = *(const float2*)(b + tid * 2);
    *(__half2*)(xo + tid * 2) = __floats2half2_rn(
        (v01.x - mu) * rstd * w01.x + b01.x,
        (v01.y - mu) * rstd * w01.y + b01.y);
    if (tid < 32) {
        const float2 w23 = *(const float2*)(w + 512 + tid * 2);
        const float2 b23 = *(const float2*)(b + 512 + tid * 2);
        *(__half2*)(xo + 512 + tid * 2) = __floats2half2_rn(
            (v23.x - mu) * rstd * w23.x + b23.x,
            (v23.y - mu) * rstd * w23.y + b23.y);
    }
}

// ---------------------------------------------------------------------------
// fp16 mma.sync GEMM (templated output): C = A @ Bt^T + bias
// BM=128, BN=192, BK=32, 4-stage cp.async, 8 warps, warp tile 64x48. 2 CTA/SM.
// A: 4x ldmatrix.x4; B: scalar LDS per-ni. Both barriers (round-12 optimum;
// do NOT perturb — B-ldmatrix and barrier-removal both regressed).
// ---------------------------------------------------------------------------
#define STG_      4
#define AROW_H    40
#define AROW_W    20
#define A_TILE_H  (128 * AROW_H)
#define B_TILE_H  (192 * AROW_H)
#define ST_H      (A_TILE_H + B_TILE_H)
#define GEMM_SMEM (STG_ * ST_H * 2)         // 102400 bytes

__device__ __forceinline__ void store2(float* p, float x, float y) {
    *(float2*)p = make_float2(x, y);
}
__device__ __forceinline__ void store2(__half* p, float x, float y) {
    *(__half2*)p = __floats2half2_rn(x, y);
}

template <typename OT>
__global__ void __launch_bounds__(256, 2) gemm_mma(
    const __half* __restrict__ A, const __half* __restrict__ Bt,
    const float* __restrict__ bias, OT* __restrict__ C,
    int N, int K)
{
    extern __shared__ __half smh[];
    const uint32_t smb = smem_to_u32(smh);

    const int tid  = threadIdx.x;
    const int wid  = tid >> 5, lane = tid & 31;
    const int bm   = blockIdx.y * 128;
    const int bn   = blockIdx.x * 192;
    const int wm   = (wid & 1) * 64;
    const int wn   = (wid >> 1) * 48;
    const int NC   = K >> 5;

    float acc[4][6][4];
    #pragma unroll
    for (int mi = 0; mi < 4; mi++)
        #pragma unroll
        for (int ni = 0; ni < 6; ni++)
            #pragma unroll
            for (int r = 0; r < 4; r++) acc[mi][ni][r] = 0.f;

    const __half* Abase  = A  + (size_t)bm * K;
    const __half* Btbase = Bt + (size_t)bn * K;

    auto load_chunk = [&](int c, int st) {
        const int k0 = c * 32;
        const uint32_t abase = smb + (st * ST_H) * 2;
        const uint32_t bbase = abase + A_TILE_H * 2;
        #pragma unroll
        for (int i = 0; i < 5; i++) {
            int u = tid + i * 256;
            if (u < 512) {
                int r = u >> 2, c4 = u & 3;
                cp16(abase + (r * AROW_H + c4 * 8) * 2,
                     Abase + (size_t)r * K + k0 + c4 * 8);
            } else {
                int w = u - 512, r = w >> 2, c4 = w & 3;
                cp16(bbase + (r * AROW_H + c4 * 8) * 2,
                     Btbase + (size_t)r * K + k0 + c4 * 8);
            }
        }
    };

    load_chunk(0, 0); cp_commit();
    if (NC > 1) load_chunk(1, 1);
    cp_commit();
    if (NC > 2) load_chunk(2, 2);
    cp_commit();

    const int lr = lane >> 2;
    const int lc = lane & 3;
    const int l16 = lane & 15;         // ldmatrix row within 16-row tile
    const int lhi = (lane >> 4) << 3;  // +8 halves for k8..15 matrices

    for (int c = 0; c < NC; c++) {
        cp_wait<2>();
        __syncthreads();
        if (c + 3 < NC) load_chunk(c + 3, (c + 3) & 3);
        cp_commit();

        const int st = c & 3;
        const uint32_t stA = smb + (st * ST_H) * 2;
        const uint32_t* Bsu = (const uint32_t*)(smh + st * ST_H + A_TILE_H);

        #pragma unroll
        for (int ks = 0; ks < 2; ks++) {
            const int kw = ks * 8 + lc;
            // A fragments: one ldmatrix.x4 per 16x16 m-tile
            uint32_t af[4][4];
            #pragma unroll
            for (int mi = 0; mi < 4; mi++) {
                uint32_t addr = stA +
                    (uint32_t)(((wm + mi * 16 + l16) * AROW_H) + ks * 16 + lhi) * 2;
                ldsm_x4(af[mi], addr);
            }
            // B fragments: scalar LDS, consumed per-ni (2 words live)
            #pragma unroll
            for (int ni = 0; ni < 6; ni++) {
                const int n0 = wn + ni * 8 + lr;
                const uint32_t b0 = Bsu[n0 * AROW_W + kw];
                const uint32_t b1 = Bsu[n0 * AROW_W + kw + 4];
                #pragma unroll
                for (int mi = 0; mi < 4; mi++)
                    mma_f16(acc[mi][ni], af[mi], b0, b1);
            }
        }
        __syncthreads();
    }

    #pragma unroll
    for (int mi = 0; mi < 4; mi++) {
        const int r0 = bm + wm + mi * 16 + lr;
        #pragma unroll
        for (int ni = 0; ni < 6; ni++) {
            const int cc = bn + wn + ni * 8 + lc * 2;
            const float b0 = bias[cc], b1 = bias[cc + 1];
            store2(C + (size_t)r0 * N + cc, acc[mi][ni][0] + b0, acc[mi][ni][1] + b1);
            store2(C + (size_t)(r0 + 8) * N + cc, acc[mi][ni][2] + b0, acc[mi][ni][3] + b1);
        }
    }
}

// ---------------------------------------------------------------------------
// Tensor-core attention, fp32 softmax. One block per (b, h), 13 warps,
// each warp one 16-row m-tile of the padded 208-row problem.
// ---------------------------------------------------------------------------
#define ATN_THREADS 416
#define QSTR  40           // halves per Q/K row (20 words)
#define VROW  136          // halves per V row (128 + pad for bank skew)
#define SM_Q  0
#define SM_K  (NP_ * QSTR)             // 8320 halves
#define SM_V  (2 * NP_ * QSTR)         // 16640 halves
#define ATT_SMEM ((SM_V + NP_ * VROW) * 2)   // 89856 bytes

__global__ void __launch_bounds__(ATN_THREADS, 1) attn_mma(
    const __half* __restrict__ qkv)
{
    extern __shared__ __align__(16) __half smh[];
    const uint32_t smb = smem_to_u32(smh);
    const int h = blockIdx.x % NH_;
    const int b = blockIdx.x / NH_;
    const int tid = threadIdx.x;
    const size_t base = (size_t)(b * N_) * HOUT_ + (size_t)h * HSZ_;

    // ---- Q,K: 208 rows x 32 halves each ----
    for (int u = tid; u < NP_ * 8; u += ATN_THREADS) {
        int j = u >> 3, c = u & 7;
        int ko = (c >= 4);
        int t  = c & 3;
        int off = (ko ? SM_K : SM_Q) + j * QSTR + t * 8;
        if (j < N_) cp16(smb + off * 2,
                         qkv + base + (size_t)j * HOUT_ + ko * 32 + t * 8);
        else *(float4*)(smh + off) = make_float4(0.f, 0.f, 0.f, 0.f);
    }
    // ---- V: 208 rows x 128 halves ----
    for (int u = tid; u < NP_ * 16; u += ATN_THREADS) {
        int j = u >> 4, c = u & 15;
        int off = SM_V + j * VROW + c * 8;
        if (j < N_) cp16(smb + off * 2,
                         qkv + base + (size_t)j * HOUT_ + 64 + c * 8);
        else *(float4*)(smh + off) = make_float4(0.f, 0.f, 0.f, 0.f);
    }
    cp_commit();
    cp_wait<0>();
    __syncthreads();

    const int w    = tid >> 5;          // 0..12
    const int lane = tid & 31;
    const int lr = lane >> 2, lc = lane & 3;
    const int m0 = w * 16;
    const int r0 = m0 + lr, r1 = r0 + 8;
    const bool vr0 = (r0 < N_), vr1 = (r1 < N_);

    const uint32_t* Qw = (const uint32_t*)(smh + SM_Q);
    const uint32_t* Kw = (const uint32_t*)(smh + SM_K);

    // Q fragments (k-tiles 0,1)
    uint32_t aq[2][4];
    #pragma unroll
    for (int kt = 0; kt < 2; kt++) {
        aq[kt][0] = Qw[r0 * 20 + kt * 8 + lc];
        aq[kt][1] = Qw[r1 * 20 + kt * 8 + lc];
        aq[kt][2] = Qw[r0 * 20 + kt * 8 + lc + 4];
        aq[kt][3] = Qw[r1 * 20 + kt * 8 + lc + 4];
    }

    const float* bias0 = g_biasf + ((size_t)h * N_ + (vr0 ? r0 : 0)) * NP_ + 2 * lc;
    const float* bias1 = g_biasf + ((size_t)h * N_ + (vr1 ? r1 : 0)) * NP_ + 2 * lc;
    const float ksc = 0.25505653946178563f;   // 32^-0.5 * log2(e)

    // ---- pass 1: row maxes (fp32) ----
    float mA = -1e30f, mB = -1e30f;
    #pragma unroll
    for (int nt = 0; nt < 26; nt++) {
        float s[4] = {0.f, 0.f, 0.f, 0.f};
        #pragma unroll
        for (int kt = 0; kt < 2; kt++) {
            uint32_t b0 = Kw[(nt * 8 + lr) * 20 + kt * 8 + lc];
            uint32_t b1 = Kw[(nt * 8 + lr) * 20 + kt * 8 + lc + 4];
            mma_f16(s, aq[kt], b0, b1);
        }
        const float2 bb0 = *(const float2*)(bias0 + nt * 8);
        const float2 bb1 = *(const float2*)(bias1 + nt * 8);
        mA = fmaxf(mA, fmaxf(fmaf(s[0], ksc, bb0.x), fmaf(s[1], ksc, bb0.y)));
        mB = fmaxf(mB, fmaxf(fmaf(s[2], ksc, bb1.x), fmaf(s[3], ksc, bb1.y)));
    }
    #pragma unroll
    for (int o = 1; o <= 2; o <<= 1) {
        mA = fmaxf(mA, __shfl_xor_sync(0xffffffffu, mA, o));
        mB = fmaxf(mB, __shfl_xor_sync(0xffffffffu, mB, o));
    }

    // ---- pass 2: P = ex2(y - max) fp32, pack to half; fp32 row sums ----
    uint32_t p01[26], p23[26];
    float sA = 0.f, sB = 0.f;
    #pragma unroll
    for (int nt = 0; nt < 26; nt++) {
        float s[4] = {0.f, 0.f, 0.f, 0.f};
        #pragma unroll
        for (int kt = 0; kt < 2; kt++) {
            uint32_t b0 = Kw[(nt * 8 + lr) * 20 + kt * 8 + lc];
            uint32_t b1 = Kw[(nt * 8 + lr) * 20 + kt * 8 + lc + 4];
            mma_f16(s, aq[kt], b0, b1);
        }
        const float2 bb0 = *(const float2*)(bias0 + nt * 8);
        const float2 bb1 = *(const float2*)(bias1 + nt * 8);
        float e0 = ex2f(fmaf(s[0], ksc, bb0.x) - mA);
        float e1 = ex2f(fmaf(s[1], ksc, bb0.y) - mA);
        float e2 = ex2f(fmaf(s[2], ksc, bb1.x) - mB);
        float e3 = ex2f(fmaf(s[3], ksc, bb1.y) - mB);
        __half2 h01 = __floats2half2_rn(e0, e1);
        __half2 h23 = __floats2half2_rn(e2, e3);
        p01[nt] = *(uint32_t*)&h01;
        p23[nt] = *(uint32_t*)&h23;
        sA += e0 + e1;
        sB += e2 + e3;
    }
    #pragma unroll
    for (int o = 1; o <= 2; o <<= 1) {
        sA += __shfl_xor_sync(0xffffffffu, sA, o);
        sB += __shfl_xor_sync(0xffffffffu, sB, o);
    }
    const float inva = __fdividef(1.f, sA);
    const float invb = __fdividef(1.f, sB);

    // ---- O = P V (8 groups of 16 cols), normalize at store ----
    const uint32_t vbytes = smb + SM_V * 2;
    const uint32_t lrow = (uint32_t)(lane & 15);
    const uint32_t lcol = (uint32_t)((lane >> 4) << 3);
    const size_t orow0 = ((size_t)(b * N_) + r0) * DH_ + h * DV_;
    const size_t orow1 = ((size_t)(b * N_) + r1) * DH_ + h * DV_;
    #pragma unroll
    for (int dg = 0; dg < 8; dg++) {
        float o2[8] = {0.f,0.f,0.f,0.f,0.f,0.f,0.f,0.f};
        uint32_t a32 = vbytes + (lrow * VROW + (uint32_t)dg * 16 + lcol) * 2;
        #pragma unroll
        for (int kt = 0; kt < 13; kt++) {
            uint32_t br[4];
            ldsm_x4_t(br, a32 + (uint32_t)kt * (16 * VROW * 2));
            uint32_t af[4] = { p01[2*kt], p23[2*kt], p01[2*kt+1], p23[2*kt+1] };
            mma_f16(o2,     af, br[0], br[1]);
            mma_f16(o2 + 4, af, br[2], br[3]);
        }
        const int c0 = dg * 16 + lc * 2;
        const int c1 = c0 + 8;
        if (vr0) {
            *(__half2*)(g_ao + orow0 + c0) = __floats2half2_rn(o2[0]*inva, o2[1]*inva);
            *(__half2*)(g_ao + orow0 + c1) = __floats2half2_rn(o2[4]*inva, o2[5]*inva);
        }
        if (vr1) {
            *(__half2*)(g_ao + orow1 + c0) = __floats2half2_rn(o2[2]*invb, o2[3]*invb);
            *(__half2*)(g_ao + orow1 + c1) = __floats2half2_rn(o2[6]*invb, o2[7]*invb);
        }
    }
}

// ---------------------------------------------------------------------------
extern "C" void kernel_launch(void* const* d_in, const int* in_sizes, int n_in,
                              void* d_out, int out_size)
{
    const float* x      = (const float*)d_in[0];
    const float* ln_w   = (const float*)d_in[1];
    const float* ln_b   = (const float*)d_in[2];
    const float* w_qkv  = (const float*)d_in[3];
    const float* b_qkv  = (const float*)d_in[4];
    const float* w_proj = (const float*)d_in[5];
    const float* b_proj = (const float*)d_in[6];
    const float* ab     = (const float*)d_in[7];
    const int*   idxs   = (const int*)d_in[8];
    float* out = (float*)d_out;
    const int offsz = in_sizes[7] / NH_;

    __half *xn_p, *qkv_p, *ao_p, *wqkvt_p, *wprojt_p;
    cudaGetSymbolAddress((void**)&xn_p,     g_xn);
    cudaGetSymbolAddress((void**)&qkv_p,    g_qkv);
    cudaGetSymbolAddress((void**)&ao_p,     g_ao);
    cudaGetSymbolAddress((void**)&wqkvt_p,  g_wqkvt);
    cudaGetSymbolAddress((void**)&wprojt_p, g_wprojt);

    // 0) Weight transposes (fp32 -> fp16) and bias expansion
    transpose_h<<<dim3(HOUT_ / 32, DIM_ / 32), dim3(32, 8)>>>(
        w_qkv, wqkvt_p, DIM_, HOUT_);
    transpose_h<<<dim3(DIM_ / 32, DH_ / 32), dim3(32, 8)>>>(
        w_proj, wprojt_p, DH_, DIM_);
    bias_expand<<<dim3(N_, NH_), 256>>>(ab, idxs, offsz);

    // 1) LayerNorm (fp16 out, float2 loads)
    ln_kernel<<<MT_, 256>>>(x, ln_w, ln_b);

    // 2) QKV GEMM: [50176,576] @ [576,3456] -> fp16
    cudaFuncSetAttribute(gemm_mma<__half>,
                         cudaFuncAttributeMaxDynamicSharedMemorySize, GEMM_SMEM);
    gemm_mma<__half><<<dim3(HOUT_ / 192, MT_ / 128), 256, GEMM_SMEM>>>(
        xn_p, wqkvt_p, b_qkv, qkv_p, HOUT_, DIM_);

    // 3) Tensor-core attention per (b, h)
    cudaFuncSetAttribute(attn_mma,
                         cudaFuncAttributeMaxDynamicSharedMemorySize, ATT_SMEM);
    attn_mma<<<B_ * NH_, ATN_THREADS, ATT_SMEM>>>(qkv_p);

    // 4) Projection GEMM: [50176,2304] @ [2304,576] -> fp32 output
    cudaFuncSetAttribute(gemm_mma<float>,
                         cudaFuncAttributeMaxDynamicSharedMemorySize, GEMM_SMEM);
    gemm_mma<float><<<dim3(DIM_ / 192, MT_ / 128), 256, GEMM_SMEM>>>(
        ao_p, wprojt_p, b_proj, out, DIM_, DH_);

    (void)n_in; (void)out_size;
}

// round 16
// speedup vs baseline: 1.5275x; 1.0048x over previous
#include <cuda_runtime.h>
#include <cuda_fp16.h>
#include <math_constants.h>
#include <cstdint>

#define B_    256
#define N_    196
#define DIM_  576
#define NH_   18
#define KD_   32
#define DV_   128
#define HSZ_  192
#define HOUT_ 3456
#define DH_   2304
#define MT_   (B_*N_)      // 50176 rows
#define NP_   208          // padded attention length (13*16)

// Scratch (allocation-free rule: static __device__ arrays)
__device__ __half g_xn [(size_t)MT_ * DIM_];        // normalized x (fp16)
__device__ __half g_qkv[(size_t)MT_ * HOUT_];       // qkv projection (fp16)
__device__ __half g_ao [(size_t)MT_ * DH_];         // attention output (fp16)
__device__ __half g_wqkvt [(size_t)HOUT_ * DIM_];   // w_qkv^T  [3456,576]
__device__ __half g_wprojt[(size_t)DIM_ * DH_];     // w_proj^T [576,2304]
__device__ float  g_biasf [(size_t)NH_ * N_ * NP_]; // bias*log2e (fp32), pad=-1e30

// ---------------------------------------------------------------------------
// helpers
// ---------------------------------------------------------------------------
__device__ __forceinline__ uint32_t smem_to_u32(const void* p) {
    uint32_t a;
    asm("{ .reg .u64 t; cvta.to.shared.u64 t, %1; cvt.u32.u64 %0, t; }"
        : "=r"(a) : "l"(p));
    return a;
}
__device__ __forceinline__ void cp16(uint32_t dst, const void* src) {
    asm volatile("cp.async.cg.shared.global [%0], [%1], 16;" :: "r"(dst), "l"(src));
}
__device__ __forceinline__ void cp_commit() {
    asm volatile("cp.async.commit_group;" ::: "memory");
}
template<int n> __device__ __forceinline__ void cp_wait() {
    asm volatile("cp.async.wait_group %0;" :: "n"(n) : "memory");
}
__device__ __forceinline__ void mma_f16(float* d, const uint32_t* a,
                                        uint32_t b0, uint32_t b1) {
    asm volatile(
        "mma.sync.aligned.m16n8k16.row.col.f32.f16.f16.f32 "
        "{%0,%1,%2,%3}, {%4,%5,%6,%7}, {%8,%9}, {%0,%1,%2,%3};\n"
        : "+f"(d[0]), "+f"(d[1]), "+f"(d[2]), "+f"(d[3])
        : "r"(a[0]), "r"(a[1]), "r"(a[2]), "r"(a[3]), "r"(b0), "r"(b1));
}
__device__ __forceinline__ void ldsm_x4(uint32_t* r, uint32_t addr) {
    asm volatile("ldmatrix.sync.aligned.m8n8.x4.shared.b16 {%0,%1,%2,%3}, [%4];"
                 : "=r"(r[0]), "=r"(r[1]), "=r"(r[2]), "=r"(r[3]) : "r"(addr));
}
__device__ __forceinline__ void ldsm_x4_t(uint32_t* r, uint32_t addr) {
    asm volatile("ldmatrix.sync.aligned.m8n8.x4.trans.shared.b16 {%0,%1,%2,%3}, [%4];"
                 : "=r"(r[0]), "=r"(r[1]), "=r"(r[2]), "=r"(r[3]) : "r"(addr));
}
__device__ __forceinline__ float ex2f(float x) {
    float y;
    asm("ex2.approx.ftz.f32 %0, %1;" : "=f"(y) : "f"(x));
    return y;
}

// ---------------------------------------------------------------------------
// Weight transpose to fp16: src[R][C] (fp32) -> dst[C][R] (fp16)
// ---------------------------------------------------------------------------
__global__ void __launch_bounds__(256) transpose_h(
    const float* __restrict__ src, __half* __restrict__ dst, int R, int C)
{
    __shared__ float t[32][33];
    const int bx = blockIdx.x * 32;
    const int by = blockIdx.y * 32;
    const int tx = threadIdx.x, ty = threadIdx.y;
    #pragma unroll
    for (int i = 0; i < 32; i += 8)
        t[ty + i][tx] = src[(size_t)(by + ty + i) * C + bx + tx];
    __syncthreads();
    #pragma unroll
    for (int i = 0; i < 32; i += 8)
        dst[(size_t)(bx + ty + i) * R + by + tx] = __float2half_rn(t[tx][ty + i]);
}

// ---------------------------------------------------------------------------
// Bias expansion: g_biasf[h][i][j] = ab[h][idxs[i][j]] * log2e; pad = -1e30
// ---------------------------------------------------------------------------
__global__ void __launch_bounds__(256) bias_expand(
    const float* __restrict__ ab, const int* __restrict__ idxs, int offsz)
{
    const int i = blockIdx.x;
    const int h = blockIdx.y;
    const float* abh = ab + (size_t)h * offsz;
    float* dst = g_biasf + ((size_t)h * N_ + i) * NP_;
    for (int j = threadIdx.x; j < NP_; j += 256)
        dst[j] = (j < N_) ? abh[idxs[i * N_ + j]] * 1.4426950408889634f
                          : -1e30f;
}

// ---------------------------------------------------------------------------
// LayerNorm: one WARP per row (576 elems = 9 float2/lane), shuffle-only
// reduction, no smem, no block barrier. 8 rows per 256-thread block.
// ---------------------------------------------------------------------------
__global__ void __launch_bounds__(256) ln_kernel(const float* __restrict__ x,
                                                 const float* __restrict__ w,
                                                 const float* __restrict__ b)
{
    const int warp = threadIdx.x >> 5, lane = threadIdx.x & 31;
    const int row  = blockIdx.x * 8 + warp;
    const float* xr = x    + (size_t)row * DIM_;
    __half*      xo = g_xn + (size_t)row * DIM_;

    float2 v[9];
    float s = 0.f, ss = 0.f;
    #pragma unroll
    for (int k = 0; k < 9; k++) {
        v[k] = *(const float2*)(xr + k * 64 + lane * 2);
        s  += v[k].x + v[k].y;
        ss += v[k].x * v[k].x + v[k].y * v[k].y;
    }
    #pragma unroll
    for (int o = 16; o; o >>= 1) {
        s  += __shfl_xor_sync(0xffffffffu, s,  o);
        ss += __shfl_xor_sync(0xffffffffu, ss, o);
    }
    const float mu   = s * (1.0f / DIM_);
    const float var  = ss * (1.0f / DIM_) - mu * mu;
    const float rstd = rsqrtf(var + 1e-5f);

    #pragma unroll
    for (int k = 0; k < 9; k++) {
        const float2 wv = *(const float2*)(w + k * 64 + lane * 2);
        const float2 bv = *(const float2*)(b + k * 64 + lane * 2);
        *(__half2*)(xo + k * 64 + lane * 2) = __floats2half2_rn(
            (v[k].x - mu) * rstd * wv.x + bv.x,
            (v[k].y - mu) * rstd * wv.y + bv.y);
    }
}

// ---------------------------------------------------------------------------
// fp16 mma.sync GEMM (templated output): C = A @ Bt^T + bias
// BM=128, BN=192, BK=32, 4-stage cp.async, 8 warps, warp tile 64x48. 2 CTA/SM.
// A: 4x ldmatrix.x4; B: scalar LDS per-ni. FROZEN round-12 optimum.
// ---------------------------------------------------------------------------
#define STG_      4
#define AROW_H    40
#define AROW_W    20
#define A_TILE_H  (128 * AROW_H)
#define B_TILE_H  (192 * AROW_H)
#define ST_H      (A_TILE_H + B_TILE_H)
#define GEMM_SMEM (STG_ * ST_H * 2)         // 102400 bytes

__device__ __forceinline__ void store2(float* p, float x, float y) {
    *(float2*)p = make_float2(x, y);
}
__device__ __forceinline__ void store2(__half* p, float x, float y) {
    *(__half2*)p = __floats2half2_rn(x, y);
}

template <typename OT>
__global__ void __launch_bounds__(256, 2) gemm_mma(
    const __half* __restrict__ A, const __half* __restrict__ Bt,
    const float* __restrict__ bias, OT* __restrict__ C,
    int N, int K)
{
    extern __shared__ __half smh[];
    const uint32_t smb = smem_to_u32(smh);

    const int tid  = threadIdx.x;
    const int wid  = tid >> 5, lane = tid & 31;
    const int bm   = blockIdx.y * 128;
    const int bn   = blockIdx.x * 192;
    const int wm   = (wid & 1) * 64;
    const int wn   = (wid >> 1) * 48;
    const int NC   = K >> 5;

    float acc[4][6][4];
    #pragma unroll
    for (int mi = 0; mi < 4; mi++)
        #pragma unroll
        for (int ni = 0; ni < 6; ni++)
            #pragma unroll
            for (int r = 0; r < 4; r++) acc[mi][ni][r] = 0.f;

    const __half* Abase  = A  + (size_t)bm * K;
    const __half* Btbase = Bt + (size_t)bn * K;

    auto load_chunk = [&](int c, int st) {
        const int k0 = c * 32;
        const uint32_t abase = smb + (st * ST_H) * 2;
        const uint32_t bbase = abase + A_TILE_H * 2;
        #pragma unroll
        for (int i = 0; i < 5; i++) {
            int u = tid + i * 256;
            if (u < 512) {
                int r = u >> 2, c4 = u & 3;
                cp16(abase + (r * AROW_H + c4 * 8) * 2,
                     Abase + (size_t)r * K + k0 + c4 * 8);
            } else {
                int w = u - 512, r = w >> 2, c4 = w & 3;
                cp16(bbase + (r * AROW_H + c4 * 8) * 2,
                     Btbase + (size_t)r * K + k0 + c4 * 8);
            }
        }
    };

    load_chunk(0, 0); cp_commit();
    if (NC > 1) load_chunk(1, 1);
    cp_commit();
    if (NC > 2) load_chunk(2, 2);
    cp_commit();

    const int lr = lane >> 2;
    const int lc = lane & 3;
    const int l16 = lane & 15;
    const int lhi = (lane >> 4) << 3;

    for (int c = 0; c < NC; c++) {
        cp_wait<2>();
        __syncthreads();
        if (c + 3 < NC) load_chunk(c + 3, (c + 3) & 3);
        cp_commit();

        const int st = c & 3;
        const uint32_t stA = smb + (st * ST_H) * 2;
        const uint32_t* Bsu = (const uint32_t*)(smh + st * ST_H + A_TILE_H);

        #pragma unroll
        for (int ks = 0; ks < 2; ks++) {
            const int kw = ks * 8 + lc;
            uint32_t af[4][4];
            #pragma unroll
            for (int mi = 0; mi < 4; mi++) {
                uint32_t addr = stA +
                    (uint32_t)(((wm + mi * 16 + l16) * AROW_H) + ks * 16 + lhi) * 2;
                ldsm_x4(af[mi], addr);
            }
            #pragma unroll
            for (int ni = 0; ni < 6; ni++) {
                const int n0 = wn + ni * 8 + lr;
                const uint32_t b0 = Bsu[n0 * AROW_W + kw];
                const uint32_t b1 = Bsu[n0 * AROW_W + kw + 4];
                #pragma unroll
                for (int mi = 0; mi < 4; mi++)
                    mma_f16(acc[mi][ni], af[mi], b0, b1);
            }
        }
        __syncthreads();
    }

    #pragma unroll
    for (int mi = 0; mi < 4; mi++) {
        const int r0 = bm + wm + mi * 16 + lr;
        #pragma unroll
        for (int ni = 0; ni < 6; ni++) {
            const int cc = bn + wn + ni * 8 + lc * 2;
            const float b0 = bias[cc], b1 = bias[cc + 1];
            store2(C + (size_t)r0 * N + cc, acc[mi][ni][0] + b0, acc[mi][ni][1] + b1);
            store2(C + (size_t)(r0 + 8) * N + cc, acc[mi][ni][2] + b0, acc[mi][ni][3] + b1);
        }
    }
}

// ---------------------------------------------------------------------------
// Tensor-core attention, single S pass: logits stored packed half2,
// softmax applied in-place (unpack -> ex2 -> repack). fp32 max/sums.
// One block per (b, h), 13 warps, each owning one 16-row m-tile.
// ---------------------------------------------------------------------------
#define ATN_THREADS 416
#define QSTR  40           // halves per Q/K row (20 words)
#define VROW  136          // halves per V row (128 + pad for bank skew)
#define SM_Q  0
#define SM_K  (NP_ * QSTR)             // 8320 halves
#define SM_V  (2 * NP_ * QSTR)         // 16640 halves
#define ATT_SMEM ((SM_V + NP_ * VROW) * 2)   // 89856 bytes

__global__ void __launch_bounds__(ATN_THREADS, 1) attn_mma(
    const __half* __restrict__ qkv)
{
    extern __shared__ __align__(16) __half smh[];
    const uint32_t smb = smem_to_u32(smh);
    const int h = blockIdx.x % NH_;
    const int b = blockIdx.x / NH_;
    const int tid = threadIdx.x;
    const size_t base = (size_t)(b * N_) * HOUT_ + (size_t)h * HSZ_;

    // ---- Q,K: 208 rows x 32 halves each ----
    for (int u = tid; u < NP_ * 8; u += ATN_THREADS) {
        int j = u >> 3, c = u & 7;
        int ko = (c >= 4);
        int t  = c & 3;
        int off = (ko ? SM_K : SM_Q) + j * QSTR + t * 8;
        if (j < N_) cp16(smb + off * 2,
                         qkv + base + (size_t)j * HOUT_ + ko * 32 + t * 8);
        else *(float4*)(smh + off) = make_float4(0.f, 0.f, 0.f, 0.f);
    }
    // ---- V: 208 rows x 128 halves ----
    for (int u = tid; u < NP_ * 16; u += ATN_THREADS) {
        int j = u >> 4, c = u & 15;
        int off = SM_V + j * VROW + c * 8;
        if (j < N_) cp16(smb + off * 2,
                         qkv + base + (size_t)j * HOUT_ + 64 + c * 8);
        else *(float4*)(smh + off) = make_float4(0.f, 0.f, 0.f, 0.f);
    }
    cp_commit();
    cp_wait<0>();
    __syncthreads();

    const int w    = tid >> 5;          // 0..12
    const int lane = tid & 31;
    const int lr = lane >> 2, lc = lane & 3;
    const int m0 = w * 16;
    const int r0 = m0 + lr, r1 = r0 + 8;
    const bool vr0 = (r0 < N_), vr1 = (r1 < N_);

    const uint32_t* Qw = (const uint32_t*)(smh + SM_Q);
    const uint32_t* Kw = (const uint32_t*)(smh + SM_K);

    // Q fragments (k-tiles 0,1)
    uint32_t aq[2][4];
    #pragma unroll
    for (int kt = 0; kt < 2; kt++) {
        aq[kt][0] = Qw[r0 * 20 + kt * 8 + lc];
        aq[kt][1] = Qw[r1 * 20 + kt * 8 + lc];
        aq[kt][2] = Qw[r0 * 20 + kt * 8 + lc + 4];
        aq[kt][3] = Qw[r1 * 20 + kt * 8 + lc + 4];
    }

    const float* bias0 = g_biasf + ((size_t)h * N_ + (vr0 ? r0 : 0)) * NP_ + 2 * lc;
    const float* bias1 = g_biasf + ((size_t)h * N_ + (vr1 ? r1 : 0)) * NP_ + 2 * lc;
    const float ksc = 0.25505653946178563f;   // 32^-0.5 * log2(e)

    // ---- single S pass: y = s*ksc + bias, store packed half2, track max ----
    uint32_t y01[26], y23[26];
    float mA = -1e30f, mB = -1e30f;
    #pragma unroll
    for (int nt = 0; nt < 26; nt++) {
        float s[4] = {0.f, 0.f, 0.f, 0.f};
        #pragma unroll
        for (int kt = 0; kt < 2; kt++) {
            uint32_t b0 = Kw[(nt * 8 + lr) * 20 + kt * 8 + lc];
            uint32_t b1 = Kw[(nt * 8 + lr) * 20 + kt * 8 + lc + 4];
            mma_f16(s, aq[kt], b0, b1);
        }
        const float2 bb0 = *(const float2*)(bias0 + nt * 8);
        const float2 bb1 = *(const float2*)(bias1 + nt * 8);
        const float y0 = fmaf(s[0], ksc, bb0.x);
        const float y1 = fmaf(s[1], ksc, bb0.y);
        const float y2 = fmaf(s[2], ksc, bb1.x);
        const float y3 = fmaf(s[3], ksc, bb1.y);
        mA = fmaxf(mA, fmaxf(y0, y1));
        mB = fmaxf(mB, fmaxf(y2, y3));
        __half2 h01 = __floats2half2_rn(y0, y1);
        __half2 h23 = __floats2half2_rn(y2, y3);
        y01[nt] = *(uint32_t*)&h01;
        y23[nt] = *(uint32_t*)&h23;
    }
    #pragma unroll
    for (int o = 1; o <= 2; o <<= 1) {
        mA = fmaxf(mA, __shfl_xor_sync(0xffffffffu, mA, o));
        mB = fmaxf(mB, __shfl_xor_sync(0xffffffffu, mB, o));
    }

    // ---- softmax in-place: unpack, ex2(y - max), repack; fp32 sums ----
    float sA = 0.f, sB = 0.f;
    #pragma unroll
    for (int nt = 0; nt < 26; nt++) {
        const float2 f0 = __half22float2(*(__half2*)&y01[nt]);
        const float2 f1 = __half22float2(*(__half2*)&y23[nt]);
        const float e0 = ex2f(f0.x - mA);
        const float e1 = ex2f(f0.y - mA);
        const float e2 = ex2f(f1.x - mB);
        const float e3 = ex2f(f1.y - mB);
        __half2 h01 = __floats2half2_rn(e0, e1);
        __half2 h23 = __floats2half2_rn(e2, e3);
        y01[nt] = *(uint32_t*)&h01;
        y23[nt] = *(uint32_t*)&h23;
        sA += e0 + e1;
        sB += e2 + e3;
    }
    #pragma unroll
    for (int o = 1; o <= 2; o <<= 1) {
        sA += __shfl_xor_sync(0xffffffffu, sA, o);
        sB += __shfl_xor_sync(0xffffffffu, sB, o);
    }
    const float inva = __fdividef(1.f, sA);
    const float invb = __fdividef(1.f, sB);

    // ---- O = P V (8 groups of 16 cols), normalize at store ----
    const uint32_t vbytes = smb + SM_V * 2;
    const uint32_t lrow = (uint32_t)(lane & 15);
    const uint32_t lcol = (uint32_t)((lane >> 4) << 3);
    const size_t orow0 = ((size_t)(b * N_) + r0) * DH_ + h * DV_;
    const size_t orow1 = ((size_t)(b * N_) + r1) * DH_ + h * DV_;
    #pragma unroll
    for (int dg = 0; dg < 8; dg++) {
        float o2[8] = {0.f,0.f,0.f,0.f,0.f,0.f,0.f,0.f};
        uint32_t a32 = vbytes + (lrow * VROW + (uint32_t)dg * 16 + lcol) * 2;
        #pragma unroll
        for (int kt = 0; kt < 13; kt++) {
            uint32_t br[4];
            ldsm_x4_t(br, a32 + (uint32_t)kt * (16 * VROW * 2));
            uint32_t af[4] = { y01[2*kt], y23[2*kt], y01[2*kt+1], y23[2*kt+1] };
            mma_f16(o2,     af, br[0], br[1]);
            mma_f16(o2 + 4, af, br[2], br[3]);
        }
        const int c0 = dg * 16 + lc * 2;
        const int c1 = c0 + 8;
        if (vr0) {
            *(__half2*)(g_ao + orow0 + c0) = __floats2half2_rn(o2[0]*inva, o2[1]*inva);
            *(__half2*)(g_ao + orow0 + c1) = __floats2half2_rn(o2[4]*inva, o2[5]*inva);
        }
        if (vr1) {
            *(__half2*)(g_ao + orow1 + c0) = __floats2half2_rn(o2[2]*invb, o2[3]*invb);
            *(__half2*)(g_ao + orow1 + c1) = __floats2half2_rn(o2[6]*invb, o2[7]*invb);
        }
    }
}

// ---------------------------------------------------------------------------
extern "C" void kernel_launch(void* const* d_in, const int* in_sizes, int n_in,
                              void* d_out, int out_size)
{
    const float* x      = (const float*)d_in[0];
    const float* ln_w   = (const float*)d_in[1];
    const float* ln_b   = (const float*)d_in[2];
    const float* w_qkv  = (const float*)d_in[3];
    const float* b_qkv  = (const float*)d_in[4];
    const float* w_proj = (const float*)d_in[5];
    const float* b_proj = (const float*)d_in[6];
    const float* ab     = (const float*)d_in[7];
    const int*   idxs   = (const int*)d_in[8];
    float* out = (float*)d_out;
    const int offsz = in_sizes[7] / NH_;

    __half *xn_p, *qkv_p, *ao_p, *wqkvt_p, *wprojt_p;
    cudaGetSymbolAddress((void**)&xn_p,     g_xn);
    cudaGetSymbolAddress((void**)&qkv_p,    g_qkv);
    cudaGetSymbolAddress((void**)&ao_p,     g_ao);
    cudaGetSymbolAddress((void**)&wqkvt_p,  g_wqkvt);
    cudaGetSymbolAddress((void**)&wprojt_p, g_wprojt);

    // 0) Weight transposes (fp32 -> fp16) and bias expansion
    transpose_h<<<dim3(HOUT_ / 32, DIM_ / 32), dim3(32, 8)>>>(
        w_qkv, wqkvt_p, DIM_, HOUT_);
    transpose_h<<<dim3(DIM_ / 32, DH_ / 32), dim3(32, 8)>>>(
        w_proj, wprojt_p, DH_, DIM_);
    bias_expand<<<dim3(N_, NH_), 256>>>(ab, idxs, offsz);

    // 1) LayerNorm (warp-per-row, fp16 out)
    ln_kernel<<<MT_ / 8, 256>>>(x, ln_w, ln_b);

    // 2) QKV GEMM: [50176,576] @ [576,3456] -> fp16
    cudaFuncSetAttribute(gemm_mma<__half>,
                         cudaFuncAttributeMaxDynamicSharedMemorySize, GEMM_SMEM);
    gemm_mma<__half><<<dim3(HOUT_ / 192, MT_ / 128), 256, GEMM_SMEM>>>(
        xn_p, wqkvt_p, b_qkv, qkv_p, HOUT_, DIM_);

    // 3) Tensor-core attention per (b, h)
    cudaFuncSetAttribute(attn_mma,
                         cudaFuncAttributeMaxDynamicSharedMemorySize, ATT_SMEM);
    attn_mma<<<B_ * NH_, ATN_THREADS, ATT_SMEM>>>(qkv_p);

    // 4) Projection GEMM: [50176,2304] @ [2304,576] -> fp32 output
    cudaFuncSetAttribute(gemm_mma<float>,
                         cudaFuncAttributeMaxDynamicSharedMemorySize, GEMM_SMEM);
    gemm_mma<float><<<dim3(DIM_ / 192, MT_ / 128), 256, GEMM_SMEM>>>(
        ao_p, wprojt_p, b_proj, out, DIM_, DH_);

    (void)n_in; (void)out_size;
}

// round 17
// speedup vs baseline: 1.5568x; 1.0191x over previous
#include <cuda_runtime.h>
#include <cuda_fp16.h>
#include <math_constants.h>
#include <cstdint>

#define B_    256
#define N_    196
#define DIM_  576
#define NH_   18
#define KD_   32
#define DV_   128
#define HSZ_  192
#define HOUT_ 3456
#define DH_   2304
#define MT_   (B_*N_)      // 50176 rows
#define NP_   208          // padded attention length (13*16)

// Scratch (allocation-free rule: static __device__ arrays)
__device__ __half g_xn [(size_t)MT_ * DIM_];        // normalized x (fp16)
__device__ __half g_qkv[(size_t)MT_ * HOUT_];       // qkv projection (fp16)
__device__ __half g_ao [(size_t)MT_ * DH_];         // attention output (fp16)
__device__ __half g_wqkvt [(size_t)HOUT_ * DIM_];   // w_qkv^T  [3456,576]
__device__ __half g_wprojt[(size_t)DIM_ * DH_];     // w_proj^T [576,2304]
__device__ float  g_biasf [(size_t)NH_ * N_ * NP_]; // bias*log2e (fp32), pad=-1e30

// ---------------------------------------------------------------------------
// helpers
// ---------------------------------------------------------------------------
__device__ __forceinline__ uint32_t smem_to_u32(const void* p) {
    uint32_t a;
    asm("{ .reg .u64 t; cvta.to.shared.u64 t, %1; cvt.u32.u64 %0, t; }"
        : "=r"(a) : "l"(p));
    return a;
}
__device__ __forceinline__ void cp16(uint32_t dst, const void* src) {
    asm volatile("cp.async.cg.shared.global [%0], [%1], 16;" :: "r"(dst), "l"(src));
}
__device__ __forceinline__ void cp_commit() {
    asm volatile("cp.async.commit_group;" ::: "memory");
}
template<int n> __device__ __forceinline__ void cp_wait() {
    asm volatile("cp.async.wait_group %0;" :: "n"(n) : "memory");
}
__device__ __forceinline__ void mma_f16(float* d, const uint32_t* a,
                                        uint32_t b0, uint32_t b1) {
    asm volatile(
        "mma.sync.aligned.m16n8k16.row.col.f32.f16.f16.f32 "
        "{%0,%1,%2,%3}, {%4,%5,%6,%7}, {%8,%9}, {%0,%1,%2,%3};\n"
        : "+f"(d[0]), "+f"(d[1]), "+f"(d[2]), "+f"(d[3])
        : "r"(a[0]), "r"(a[1]), "r"(a[2]), "r"(a[3]), "r"(b0), "r"(b1));
}
__device__ __forceinline__ void ldsm_x4(uint32_t* r, uint32_t addr) {
    asm volatile("ldmatrix.sync.aligned.m8n8.x4.shared.b16 {%0,%1,%2,%3}, [%4];"
                 : "=r"(r[0]), "=r"(r[1]), "=r"(r[2]), "=r"(r[3]) : "r"(addr));
}
__device__ __forceinline__ void ldsm_x4_t(uint32_t* r, uint32_t addr) {
    asm volatile("ldmatrix.sync.aligned.m8n8.x4.trans.shared.b16 {%0,%1,%2,%3}, [%4];"
                 : "=r"(r[0]), "=r"(r[1]), "=r"(r[2]), "=r"(r[3]) : "r"(addr));
}
__device__ __forceinline__ float ex2f(float x) {
    float y;
    asm("ex2.approx.ftz.f32 %0, %1;" : "=f"(y) : "f"(x));
    return y;
}

// ---------------------------------------------------------------------------
// Weight transpose to fp16: src[R][C] (fp32) -> dst[C][R] (fp16)
// ---------------------------------------------------------------------------
__global__ void __launch_bounds__(256) transpose_h(
    const float* __restrict__ src, __half* __restrict__ dst, int R, int C)
{
    __shared__ float t[32][33];
    const int bx = blockIdx.x * 32;
    const int by = blockIdx.y * 32;
    const int tx = threadIdx.x, ty = threadIdx.y;
    #pragma unroll
    for (int i = 0; i < 32; i += 8)
        t[ty + i][tx] = src[(size_t)(by + ty + i) * C + bx + tx];
    __syncthreads();
    #pragma unroll
    for (int i = 0; i < 32; i += 8)
        dst[(size_t)(bx + ty + i) * R + by + tx] = __float2half_rn(t[tx][ty + i]);
}

// ---------------------------------------------------------------------------
// Bias expansion: g_biasf[h][i][j] = ab[h][idxs[i][j]] * log2e; pad = -1e30
// ---------------------------------------------------------------------------
__global__ void __launch_bounds__(256) bias_expand(
    const float* __restrict__ ab, const int* __restrict__ idxs, int offsz)
{
    const int i = blockIdx.x;
    const int h = blockIdx.y;
    const float* abh = ab + (size_t)h * offsz;
    float* dst = g_biasf + ((size_t)h * N_ + i) * NP_;
    for (int j = threadIdx.x; j < NP_; j += 256)
        dst[j] = (j < N_) ? abh[idxs[i * N_ + j]] * 1.4426950408889634f
                          : -1e30f;
}

// ---------------------------------------------------------------------------
// LayerNorm: one WARP per row (576 elems = 9 float2/lane), shuffle-only
// ---------------------------------------------------------------------------
__global__ void __launch_bounds__(256) ln_kernel(const float* __restrict__ x,
                                                 const float* __restrict__ w,
                                                 const float* __restrict__ b)
{
    const int warp = threadIdx.x >> 5, lane = threadIdx.x & 31;
    const int row  = blockIdx.x * 8 + warp;
    const float* xr = x    + (size_t)row * DIM_;
    __half*      xo = g_xn + (size_t)row * DIM_;

    float2 v[9];
    float s = 0.f, ss = 0.f;
    #pragma unroll
    for (int k = 0; k < 9; k++) {
        v[k] = *(const float2*)(xr + k * 64 + lane * 2);
        s  += v[k].x + v[k].y;
        ss += v[k].x * v[k].x + v[k].y * v[k].y;
    }
    #pragma unroll
    for (int o = 16; o; o >>= 1) {
        s  += __shfl_xor_sync(0xffffffffu, s,  o);
        ss += __shfl_xor_sync(0xffffffffu, ss, o);
    }
    const float mu   = s * (1.0f / DIM_);
    const float var  = ss * (1.0f / DIM_) - mu * mu;
    const float rstd = rsqrtf(var + 1e-5f);

    #pragma unroll
    for (int k = 0; k < 9; k++) {
        const float2 wv = *(const float2*)(w + k * 64 + lane * 2);
        const float2 bv = *(const float2*)(b + k * 64 + lane * 2);
        *(__half2*)(xo + k * 64 + lane * 2) = __floats2half2_rn(
            (v[k].x - mu) * rstd * wv.x + bv.x,
            (v[k].y - mu) * rstd * wv.y + bv.y);
    }
}

// ---------------------------------------------------------------------------
// fp16 mma.sync GEMM (templated output): C = A @ Bt^T + bias
// BM=128, BN=192, BK=32, 4-stage cp.async, 8 warps, warp tile 64x48. 2 CTA/SM.
// A: 4x ldmatrix.x4; B: scalar LDS per-ni. FROZEN round-12 optimum.
// ---------------------------------------------------------------------------
#define STG_      4
#define AROW_H    40
#define AROW_W    20
#define A_TILE_H  (128 * AROW_H)
#define B_TILE_H  (192 * AROW_H)
#define ST_H      (A_TILE_H + B_TILE_H)
#define GEMM_SMEM (STG_ * ST_H * 2)         // 102400 bytes

__device__ __forceinline__ void store2(float* p, float x, float y) {
    *(float2*)p = make_float2(x, y);
}
__device__ __forceinline__ void store2(__half* p, float x, float y) {
    *(__half2*)p = __floats2half2_rn(x, y);
}

template <typename OT>
__global__ void __launch_bounds__(256, 2) gemm_mma(
    const __half* __restrict__ A, const __half* __restrict__ Bt,
    const float* __restrict__ bias, OT* __restrict__ C,
    int N, int K)
{
    extern __shared__ __half smh[];
    const uint32_t smb = smem_to_u32(smh);

    const int tid  = threadIdx.x;
    const int wid  = tid >> 5, lane = tid & 31;
    const int bm   = blockIdx.y * 128;
    const int bn   = blockIdx.x * 192;
    const int wm   = (wid & 1) * 64;
    const int wn   = (wid >> 1) * 48;
    const int NC   = K >> 5;

    float acc[4][6][4];
    #pragma unroll
    for (int mi = 0; mi < 4; mi++)
        #pragma unroll
        for (int ni = 0; ni < 6; ni++)
            #pragma unroll
            for (int r = 0; r < 4; r++) acc[mi][ni][r] = 0.f;

    const __half* Abase  = A  + (size_t)bm * K;
    const __half* Btbase = Bt + (size_t)bn * K;

    auto load_chunk = [&](int c, int st) {
        const int k0 = c * 32;
        const uint32_t abase = smb + (st * ST_H) * 2;
        const uint32_t bbase = abase + A_TILE_H * 2;
        #pragma unroll
        for (int i = 0; i < 5; i++) {
            int u = tid + i * 256;
            if (u < 512) {
                int r = u >> 2, c4 = u & 3;
                cp16(abase + (r * AROW_H + c4 * 8) * 2,
                     Abase + (size_t)r * K + k0 + c4 * 8);
            } else {
                int w = u - 512, r = w >> 2, c4 = w & 3;
                cp16(bbase + (r * AROW_H + c4 * 8) * 2,
                     Btbase + (size_t)r * K + k0 + c4 * 8);
            }
        }
    };

    load_chunk(0, 0); cp_commit();
    if (NC > 1) load_chunk(1, 1);
    cp_commit();
    if (NC > 2) load_chunk(2, 2);
    cp_commit();

    const int lr = lane >> 2;
    const int lc = lane & 3;
    const int l16 = lane & 15;
    const int lhi = (lane >> 4) << 3;

    for (int c = 0; c < NC; c++) {
        cp_wait<2>();
        __syncthreads();
        if (c + 3 < NC) load_chunk(c + 3, (c + 3) & 3);
        cp_commit();

        const int st = c & 3;
        const uint32_t stA = smb + (st * ST_H) * 2;
        const uint32_t* Bsu = (const uint32_t*)(smh + st * ST_H + A_TILE_H);

        #pragma unroll
        for (int ks = 0; ks < 2; ks++) {
            const int kw = ks * 8 + lc;
            uint32_t af[4][4];
            #pragma unroll
            for (int mi = 0; mi < 4; mi++) {
                uint32_t addr = stA +
                    (uint32_t)(((wm + mi * 16 + l16) * AROW_H) + ks * 16 + lhi) * 2;
                ldsm_x4(af[mi], addr);
            }
            #pragma unroll
            for (int ni = 0; ni < 6; ni++) {
                const int n0 = wn + ni * 8 + lr;
                const uint32_t b0 = Bsu[n0 * AROW_W + kw];
                const uint32_t b1 = Bsu[n0 * AROW_W + kw + 4];
                #pragma unroll
                for (int mi = 0; mi < 4; mi++)
                    mma_f16(acc[mi][ni], af[mi], b0, b1);
            }
        }
        __syncthreads();
    }

    #pragma unroll
    for (int mi = 0; mi < 4; mi++) {
        const int r0 = bm + wm + mi * 16 + lr;
        #pragma unroll
        for (int ni = 0; ni < 6; ni++) {
            const int cc = bn + wn + ni * 8 + lc * 2;
            const float b0 = bias[cc], b1 = bias[cc + 1];
            store2(C + (size_t)r0 * N + cc, acc[mi][ni][0] + b0, acc[mi][ni][1] + b1);
            store2(C + (size_t)(r0 + 8) * N + cc, acc[mi][ni][2] + b0, acc[mi][ni][3] + b1);
        }
    }
}

// ---------------------------------------------------------------------------
// Tensor-core attention, single S pass, SPLIT LOAD GROUPS:
//   group 0 = Q+K (waited before S pass), group 1 = V (waited before PV).
// V load overlaps the S computation + softmax.
// ---------------------------------------------------------------------------
#define ATN_THREADS 416
#define QSTR  40           // halves per Q/K row (20 words)
#define VROW  136          // halves per V row (128 + pad for bank skew)
#define SM_Q  0
#define SM_K  (NP_ * QSTR)             // 8320 halves
#define SM_V  (2 * NP_ * QSTR)         // 16640 halves
#define ATT_SMEM ((SM_V + NP_ * VROW) * 2)   // 89856 bytes

__global__ void __launch_bounds__(ATN_THREADS, 1) attn_mma(
    const __half* __restrict__ qkv)
{
    extern __shared__ __align__(16) __half smh[];
    const uint32_t smb = smem_to_u32(smh);
    const int h = blockIdx.x % NH_;
    const int b = blockIdx.x / NH_;
    const int tid = threadIdx.x;
    const size_t base = (size_t)(b * N_) * HOUT_ + (size_t)h * HSZ_;

    // ---- group 0: Q,K (208 rows x 32 halves each) ----
    for (int u = tid; u < NP_ * 8; u += ATN_THREADS) {
        int j = u >> 3, c = u & 7;
        int ko = (c >= 4);
        int t  = c & 3;
        int off = (ko ? SM_K : SM_Q) + j * QSTR + t * 8;
        if (j < N_) cp16(smb + off * 2,
                         qkv + base + (size_t)j * HOUT_ + ko * 32 + t * 8);
        else *(float4*)(smh + off) = make_float4(0.f, 0.f, 0.f, 0.f);
    }
    cp_commit();
    // ---- group 1: V (208 rows x 128 halves) ----
    for (int u = tid; u < NP_ * 16; u += ATN_THREADS) {
        int j = u >> 4, c = u & 15;
        int off = SM_V + j * VROW + c * 8;
        if (j < N_) cp16(smb + off * 2,
                         qkv + base + (size_t)j * HOUT_ + 64 + c * 8);
        else *(float4*)(smh + off) = make_float4(0.f, 0.f, 0.f, 0.f);
    }
    cp_commit();

    cp_wait<1>();          // Q,K ready; V still in flight
    __syncthreads();

    const int w    = tid >> 5;          // 0..12
    const int lane = tid & 31;
    const int lr = lane >> 2, lc = lane & 3;
    const int m0 = w * 16;
    const int r0 = m0 + lr, r1 = r0 + 8;
    const bool vr0 = (r0 < N_), vr1 = (r1 < N_);

    const uint32_t* Qw = (const uint32_t*)(smh + SM_Q);
    const uint32_t* Kw = (const uint32_t*)(smh + SM_K);

    // Q fragments (k-tiles 0,1)
    uint32_t aq[2][4];
    #pragma unroll
    for (int kt = 0; kt < 2; kt++) {
        aq[kt][0] = Qw[r0 * 20 + kt * 8 + lc];
        aq[kt][1] = Qw[r1 * 20 + kt * 8 + lc];
        aq[kt][2] = Qw[r0 * 20 + kt * 8 + lc + 4];
        aq[kt][3] = Qw[r1 * 20 + kt * 8 + lc + 4];
    }

    const float* bias0 = g_biasf + ((size_t)h * N_ + (vr0 ? r0 : 0)) * NP_ + 2 * lc;
    const float* bias1 = g_biasf + ((size_t)h * N_ + (vr1 ? r1 : 0)) * NP_ + 2 * lc;
    const float ksc = 0.25505653946178563f;   // 32^-0.5 * log2(e)

    // ---- single S pass: y = s*ksc + bias, store packed half2, track max ----
    uint32_t y01[26], y23[26];
    float mA = -1e30f, mB = -1e30f;
    #pragma unroll
    for (int nt = 0; nt < 26; nt++) {
        float s[4] = {0.f, 0.f, 0.f, 0.f};
        #pragma unroll
        for (int kt = 0; kt < 2; kt++) {
            uint32_t b0 = Kw[(nt * 8 + lr) * 20 + kt * 8 + lc];
            uint32_t b1 = Kw[(nt * 8 + lr) * 20 + kt * 8 + lc + 4];
            mma_f16(s, aq[kt], b0, b1);
        }
        const float2 bb0 = *(const float2*)(bias0 + nt * 8);
        const float2 bb1 = *(const float2*)(bias1 + nt * 8);
        const float y0 = fmaf(s[0], ksc, bb0.x);
        const float y1 = fmaf(s[1], ksc, bb0.y);
        const float y2 = fmaf(s[2], ksc, bb1.x);
        const float y3 = fmaf(s[3], ksc, bb1.y);
        mA = fmaxf(mA, fmaxf(y0, y1));
        mB = fmaxf(mB, fmaxf(y2, y3));
        __half2 h01 = __floats2half2_rn(y0, y1);
        __half2 h23 = __floats2half2_rn(y2, y3);
        y01[nt] = *(uint32_t*)&h01;
        y23[nt] = *(uint32_t*)&h23;
    }
    #pragma unroll
    for (int o = 1; o <= 2; o <<= 1) {
        mA = fmaxf(mA, __shfl_xor_sync(0xffffffffu, mA, o));
        mB = fmaxf(mB, __shfl_xor_sync(0xffffffffu, mB, o));
    }

    // ---- softmax in-place: unpack, ex2(y - max), repack; fp32 sums ----
    float sA = 0.f, sB = 0.f;
    #pragma unroll
    for (int nt = 0; nt < 26; nt++) {
        const float2 f0 = __half22float2(*(__half2*)&y01[nt]);
        const float2 f1 = __half22float2(*(__half2*)&y23[nt]);
        const float e0 = ex2f(f0.x - mA);
        const float e1 = ex2f(f0.y - mA);
        const float e2 = ex2f(f1.x - mB);
        const float e3 = ex2f(f1.y - mB);
        __half2 h01 = __floats2half2_rn(e0, e1);
        __half2 h23 = __floats2half2_rn(e2, e3);
        y01[nt] = *(uint32_t*)&h01;
        y23[nt] = *(uint32_t*)&h23;
        sA += e0 + e1;
        sB += e2 + e3;
    }
    #pragma unroll
    for (int o = 1; o <= 2; o <<= 1) {
        sA += __shfl_xor_sync(0xffffffffu, sA, o);
        sB += __shfl_xor_sync(0xffffffffu, sB, o);
    }
    const float inva = __fdividef(1.f, sA);
    const float invb = __fdividef(1.f, sB);

    // ---- wait V, then O = P V (8 groups of 16 cols) ----
    cp_wait<0>();
    __syncthreads();

    const uint32_t vbytes = smb + SM_V * 2;
    const uint32_t lrow = (uint32_t)(lane & 15);
    const uint32_t lcol = (uint32_t)((lane >> 4) << 3);
    const size_t orow0 = ((size_t)(b * N_) + r0) * DH_ + h * DV_;
    const size_t orow1 = ((size_t)(b * N_) + r1) * DH_ + h * DV_;
    #pragma unroll
    for (int dg = 0; dg < 8; dg++) {
        float o2[8] = {0.f,0.f,0.f,0.f,0.f,0.f,0.f,0.f};
        uint32_t a32 = vbytes + (lrow * VROW + (uint32_t)dg * 16 + lcol) * 2;
        #pragma unroll
        for (int kt = 0; kt < 13; kt++) {
            uint32_t br[4];
            ldsm_x4_t(br, a32 + (uint32_t)kt * (16 * VROW * 2));
            uint32_t af[4] = { y01[2*kt], y23[2*kt], y01[2*kt+1], y23[2*kt+1] };
            mma_f16(o2,     af, br[0], br[1]);
            mma_f16(o2 + 4, af, br[2], br[3]);
        }
        const int c0 = dg * 16 + lc * 2;
        const int c1 = c0 + 8;
        if (vr0) {
            *(__half2*)(g_ao + orow0 + c0) = __floats2half2_rn(o2[0]*inva, o2[1]*inva);
            *(__half2*)(g_ao + orow0 + c1) = __floats2half2_rn(o2[4]*inva, o2[5]*inva);
        }
        if (vr1) {
            *(__half2*)(g_ao + orow1 + c0) = __floats2half2_rn(o2[2]*invb, o2[3]*invb);
            *(__half2*)(g_ao + orow1 + c1) = __floats2half2_rn(o2[6]*invb, o2[7]*invb);
        }
    }
}

// ---------------------------------------------------------------------------
extern "C" void kernel_launch(void* const* d_in, const int* in_sizes, int n_in,
                              void* d_out, int out_size)
{
    const float* x      = (const float*)d_in[0];
    const float* ln_w   = (const float*)d_in[1];
    const float* ln_b   = (const float*)d_in[2];
    const float* w_qkv  = (const float*)d_in[3];
    const float* b_qkv  = (const float*)d_in[4];
    const float* w_proj = (const float*)d_in[5];
    const float* b_proj = (const float*)d_in[6];
    const float* ab     = (const float*)d_in[7];
    const int*   idxs   = (const int*)d_in[8];
    float* out = (float*)d_out;
    const int offsz = in_sizes[7] / NH_;

    __half *xn_p, *qkv_p, *ao_p, *wqkvt_p, *wprojt_p;
    cudaGetSymbolAddress((void**)&xn_p,     g_xn);
    cudaGetSymbolAddress((void**)&qkv_p,    g_qkv);
    cudaGetSymbolAddress((void**)&ao_p,     g_ao);
    cudaGetSymbolAddress((void**)&wqkvt_p,  g_wqkvt);
    cudaGetSymbolAddress((void**)&wprojt_p, g_wprojt);

    // 0) Weight transposes (fp32 -> fp16) and bias expansion
    transpose_h<<<dim3(HOUT_ / 32, DIM_ / 32), dim3(32, 8)>>>(
        w_qkv, wqkvt_p, DIM_, HOUT_);
    transpose_h<<<dim3(DIM_ / 32, DH_ / 32), dim3(32, 8)>>>(
        w_proj, wprojt_p, DH_, DIM_);
    bias_expand<<<dim3(N_, NH_), 256>>>(ab, idxs, offsz);

    // 1) LayerNorm (warp-per-row, fp16 out)
    ln_kernel<<<MT_ / 8, 256>>>(x, ln_w, ln_b);

    // 2) QKV GEMM: [50176,576] @ [576,3456] -> fp16
    cudaFuncSetAttribute(gemm_mma<__half>,
                         cudaFuncAttributeMaxDynamicSharedMemorySize, GEMM_SMEM);
    gemm_mma<__half><<<dim3(HOUT_ / 192, MT_ / 128), 256, GEMM_SMEM>>>(
        xn_p, wqkvt_p, b_qkv, qkv_p, HOUT_, DIM_);

    // 3) Tensor-core attention per (b, h)
    cudaFuncSetAttribute(attn_mma,
                         cudaFuncAttributeMaxDynamicSharedMemorySize, ATT_SMEM);
    attn_mma<<<B_ * NH_, ATN_THREADS, ATT_SMEM>>>(qkv_p);

    // 4) Projection GEMM: [50176,2304] @ [2304,576] -> fp32 output
    cudaFuncSetAttribute(gemm_mma<float>,
                         cudaFuncAttributeMaxDynamicSharedMemorySize, GEMM_SMEM);
    gemm_mma<float><<<dim3(DIM_ / 192, MT_ / 128), 256, GEMM_SMEM>>>(
        ao_p, wprojt_p, b_proj, out, DIM_, DH_);

    (void)n_in; (void)out_size;
}